// round 10
// baseline (speedup 1.0000x reference)
#include <cuda_runtime.h>
#include <cuda_bf16.h>
#include <cstdint>

// ---------------------------------------------------------------------------
// Problem constants
// ---------------------------------------------------------------------------
#define NPTS   32768
#define FCH    64
#define MSEL   8192
#define KNBR   64
#define HID    128
#define OUTC   128

// ---------------------------------------------------------------------------
// Scratch (device globals; no allocation allowed)
// ---------------------------------------------------------------------------
__device__ float g_selpos[MSEL * 3];                 // FPS-selected positions
__device__ float g_hpre[NPTS * HID];                 // per-point layer-1 pre-activation
__device__ int   g_nbr[MSEL * KNBR];                 // neighbor indices (valid [0,cnt))
__device__ int   g_ncnt[MSEL];                       // neighbor counts

__device__ __forceinline__ float d2_exact(float dx, float dy, float dz) {
    // Match XLA: elementwise square then add-reduce, NO fma contraction.
    return __fadd_rn(__fadd_rn(__fmul_rn(dx, dx), __fmul_rn(dy, dy)),
                     __fmul_rn(dz, dz));
}

// ===========================================================================
// Stage A: farthest point sampling.  4-CTA cluster, one persistent pass.
// Each of 4*512 threads owns 16 points in registers (pos + running min-dist).
// One cluster barrier per iteration; parity-double-buffered DSMEM mailbox.
// ===========================================================================
#define FPS_THREADS 512
#define FPS_PTS     16

__global__ void __cluster_dims__(4, 1, 1) __launch_bounds__(FPS_THREADS, 1)
fps_kernel(const float* __restrict__ pos)
{
    __shared__ float    sv[16], sx_[16], sy_[16], sz_[16];
    __shared__ unsigned si[16];
    __shared__ unsigned mbox[2][4][8];   // [parity][src rank][v,idx,x,y,z,...]

    const int tid  = threadIdx.x;
    const int rank = blockIdx.x;           // cluster rank == blockIdx (grid = 1 cluster)
    const int lane = tid & 31;
    const int warp = tid >> 5;
    const float NEG_INF = __int_as_float(0xff800000);
    const float POS_INF = __int_as_float(0x7f800000);

    float px[FPS_PTS], py[FPS_PTS], pz[FPS_PTS], mind[FPS_PTS];
    const unsigned pbase = rank * 8192u + (unsigned)tid;   // + j*512

#pragma unroll
    for (int j = 0; j < FPS_PTS; j++) {
        unsigned g = pbase + j * 512u;
        px[j] = pos[3u * g];
        py[j] = pos[3u * g + 1];
        pz[j] = pos[3u * g + 2];
        mind[j] = POS_INF;
    }

    // winner = point 0 (seed)
    float wx = pos[0], wy = pos[1], wz = pos[2];
    if (rank == 0 && tid == 0) {
        g_selpos[0] = wx; g_selpos[1] = wy; g_selpos[2] = wz;
    }

    for (int i = 1; i < MSEL; ++i) {
        // ---- fused min-dist update (vs previous winner) + local argmax ----
        float    bv = NEG_INF, bx = 0.f, by = 0.f, bz = 0.f;
        unsigned bi = 0xffffffffu;
#pragma unroll
        for (int j = 0; j < FPS_PTS; j++) {
            float dx = px[j] - wx, dy = py[j] - wy, dz = pz[j] - wz;
            float d2 = d2_exact(dx, dy, dz);
            float m  = fminf(mind[j], d2);
            mind[j]  = m;
            if (m > bv) {   // strict >  => smallest index wins on tie
                bv = m; bi = pbase + j * 512u;
                bx = px[j]; by = py[j]; bz = pz[j];
            }
        }
        // ---- warp butterfly reduce: (max v, min idx) carrying xyz ----
#pragma unroll
        for (int off = 16; off; off >>= 1) {
            float    ov = __shfl_xor_sync(0xffffffffu, bv, off);
            unsigned oi = __shfl_xor_sync(0xffffffffu, bi, off);
            float    ox = __shfl_xor_sync(0xffffffffu, bx, off);
            float    oy = __shfl_xor_sync(0xffffffffu, by, off);
            float    oz = __shfl_xor_sync(0xffffffffu, bz, off);
            if (ov > bv || (ov == bv && oi < bi)) {
                bv = ov; bi = oi; bx = ox; by = oy; bz = oz;
            }
        }
        if (lane == 0) { sv[warp] = bv; si[warp] = bi; sx_[warp] = bx; sy_[warp] = by; sz_[warp] = bz; }
        __syncthreads();

        const int par = i & 1;
        if (warp == 0) {
            float cv, cx, cy, cz; unsigned ci;
            if (lane < 16) { cv = sv[lane]; ci = si[lane]; cx = sx_[lane]; cy = sy_[lane]; cz = sz_[lane]; }
            else           { cv = NEG_INF;  ci = 0xffffffffu; cx = cy = cz = 0.f; }
#pragma unroll
            for (int off = 16; off; off >>= 1) {
                float    ov = __shfl_xor_sync(0xffffffffu, cv, off);
                unsigned oi = __shfl_xor_sync(0xffffffffu, ci, off);
                float    ox = __shfl_xor_sync(0xffffffffu, cx, off);
                float    oy = __shfl_xor_sync(0xffffffffu, cy, off);
                float    oz = __shfl_xor_sync(0xffffffffu, cz, off);
                if (ov > cv || (ov == cv && oi < ci)) {
                    cv = ov; ci = oi; cx = ox; cy = oy; cz = oz;
                }
            }
            if (lane < 4) {   // lane L -> deliver this CTA's candidate to rank L
                uint32_t la = (uint32_t)__cvta_generic_to_shared(&mbox[par][rank][0]);
                uint32_t ra;
                asm volatile("mapa.shared::cluster.u32 %0, %1, %2;"
                             : "=r"(ra) : "r"(la), "r"((unsigned)lane));
                asm volatile("st.shared::cluster.b32 [%0],    %1;" :: "r"(ra), "r"(__float_as_uint(cv)) : "memory");
                asm volatile("st.shared::cluster.b32 [%0+4],  %1;" :: "r"(ra), "r"(ci)                   : "memory");
                asm volatile("st.shared::cluster.b32 [%0+8],  %1;" :: "r"(ra), "r"(__float_as_uint(cx)) : "memory");
                asm volatile("st.shared::cluster.b32 [%0+12], %1;" :: "r"(ra), "r"(__float_as_uint(cy)) : "memory");
                asm volatile("st.shared::cluster.b32 [%0+16], %1;" :: "r"(ra), "r"(__float_as_uint(cz)) : "memory");
            }
        }
        // release (our stores) / acquire (remote stores)
        asm volatile("barrier.cluster.arrive.aligned;" ::: "memory");
        asm volatile("barrier.cluster.wait.aligned;"   ::: "memory");

        // ---- every thread computes the identical global winner ----
        float wv = NEG_INF; unsigned wbi = 0xffffffffu;
#pragma unroll
        for (int r = 0; r < 4; r++) {
            float    v  = __uint_as_float(mbox[par][r][0]);
            unsigned ix = mbox[par][r][1];
            float    xx = __uint_as_float(mbox[par][r][2]);
            float    yy = __uint_as_float(mbox[par][r][3]);
            float    zz = __uint_as_float(mbox[par][r][4]);
            if (v > wv || (v == wv && ix < wbi)) {
                wv = v; wbi = ix; wx = xx; wy = yy; wz = zz;
            }
        }
        if (rank == 0 && tid == 0) {
            g_selpos[3 * i]     = wx;
            g_selpos[3 * i + 1] = wy;
            g_selpos[3 * i + 2] = wz;
        }
    }
}

// ===========================================================================
// Stage C0: h_pre[j][ch] = b1[ch] + x[j,:]@W1[:64,ch] + pos[j,:]@W1[64:67,ch]
// 512 CTAs x 128 threads; thread = channel, W1 column in registers.
// ===========================================================================
__global__ void __launch_bounds__(128)
hpre_kernel(const float* __restrict__ x, const float* __restrict__ pos,
            const float* __restrict__ W1, const float* __restrict__ b1)
{
    const int t = threadIdx.x;
    float w1c[FCH + 3];
#pragma unroll
    for (int f = 0; f < FCH + 3; f++) w1c[f] = W1[f * HID + t];
    const float bb = b1[t];

    __shared__ float xs[FCH];
    __shared__ float ps[3];

    const int row0 = blockIdx.x * 64;
    for (int r = 0; r < 64; r++) {
        const int row = row0 + r;
        if (t < FCH) xs[t] = x[row * FCH + t];
        if (t < 3)   ps[t] = pos[row * 3 + t];
        __syncthreads();
        float acc = bb;
        acc = fmaf(ps[0], w1c[64], acc);
        acc = fmaf(ps[1], w1c[65], acc);
        acc = fmaf(ps[2], w1c[66], acc);
#pragma unroll
        for (int f = 0; f < FCH; f++) acc = fmaf(xs[f], w1c[f], acc);
        g_hpre[row * HID + t] = acc;
        __syncthreads();
    }
}

// ===========================================================================
// Stage B: radius neighbors. 256 CTAs x 256 threads; warp handles 4 centroids.
// Collect in-radius candidates into SMEM, warp-bitonic sort (d2 asc, idx asc),
// emit min(cnt,64) nearest -> identical set/tie semantics to masked top_k.
// ===========================================================================
#define NB_THREADS 256
#define NB_CPW     4
#define NB_CPB     32
#define NB_TILE    2048
#define NB_CAP     256
#define NB_SMEM    (NB_TILE * 16 + NB_CPB * NB_CAP * 8)

__global__ void __launch_bounds__(NB_THREADS)
nbr_kernel(const float* __restrict__ pos)
{
    extern __shared__ char smemraw[];
    float4* ptile = (float4*)smemraw;
    unsigned long long (*cand)[NB_CAP] =
        (unsigned long long (*)[NB_CAP])(smemraw + NB_TILE * 16);

    const int lane  = threadIdx.x & 31;
    const int warp  = threadIdx.x >> 5;
    const int cbase = blockIdx.x * NB_CPB + warp * NB_CPW;
    const float R2  = (float)(0.08 * 0.08);   // match python f64 -> f32 scalar

    float cx[NB_CPW], cy[NB_CPW], cz[NB_CPW];
    int cnt[NB_CPW];
#pragma unroll
    for (int c = 0; c < NB_CPW; c++) {
        int ci = cbase + c;
        cx[c] = g_selpos[3 * ci]; cy[c] = g_selpos[3 * ci + 1]; cz[c] = g_selpos[3 * ci + 2];
        cnt[c] = 0;
    }

    for (int tb = 0; tb < NPTS; tb += NB_TILE) {
        __syncthreads();
        for (int s = threadIdx.x; s < NB_TILE; s += NB_THREADS) {
            int g = tb + s;
            ptile[s] = make_float4(pos[3 * g], pos[3 * g + 1], pos[3 * g + 2], 0.f);
        }
        __syncthreads();
#pragma unroll
        for (int c = 0; c < NB_CPW; c++) {
            const int row = warp * NB_CPW + c;
            for (int s = lane; s < NB_TILE; s += 32) {
                float4 p = ptile[s];
                float d2 = d2_exact(cx[c] - p.x, cy[c] - p.y, cz[c] - p.z);
                bool pred = (d2 <= R2);
                unsigned m = __ballot_sync(0xffffffffu, pred);
                if (pred) {
                    int slot = cnt[c] + __popc(m & ((1u << lane) - 1u));
                    if (slot < NB_CAP)
                        cand[row][slot] =
                            ((unsigned long long)__float_as_uint(d2) << 32) |
                            (unsigned)(tb + s);
                }
                cnt[c] += __popc(m);
            }
        }
    }

    // sort + emit
#pragma unroll
    for (int c = 0; c < NB_CPW; c++) {
        const int row = warp * NB_CPW + c;
        const int ci  = cbase + c;
        const int n   = min(cnt[c], NB_CAP);
        unsigned long long* a = cand[row];
        for (int e = lane; e < NB_CAP; e += 32)
            if (e >= n) a[e] = 0xffffffffffffffffull;
        __syncwarp();
        // bitonic sort ascending (256 keys)
        for (int k = 2; k <= NB_CAP; k <<= 1) {
            for (int j = k >> 1; j > 0; j >>= 1) {
                __syncwarp();
                for (int e = lane; e < NB_CAP; e += 32) {
                    int p = e ^ j;
                    if (p > e) {
                        unsigned long long va = a[e], vb = a[p];
                        bool up = ((e & k) == 0);
                        if ((va > vb) == up) { a[e] = vb; a[p] = va; }
                    }
                }
            }
        }
        __syncwarp();
        const int m = min(n, KNBR);
        for (int k = lane; k < KNBR; k += 32)
            g_nbr[ci * KNBR + k] = (k < m) ? (int)(a[k] & 0xffffffffu) : -1;
        if (lane == 0) g_ncnt[ci] = m;
        __syncwarp();
    }
}

// ===========================================================================
// Stage C: out[i][t] = b2[t] + max_k  relu(h_pre[nbr] - selpos_i@W1[64:67]) @ W2[:,t]
// 512 CTAs x 128 threads; W2 column register-resident; prefetched h_pre rows.
// ===========================================================================
#define CV_CENT 16

__global__ void __launch_bounds__(128)
conv_kernel(const float* __restrict__ W1, const float* __restrict__ W2,
            const float* __restrict__ b2, float* __restrict__ dout, int out_size)
{
    const int t = threadIdx.x;
    float w2c[HID];
#pragma unroll
    for (int h = 0; h < HID; h++) w2c[h] = W2[h * OUTC + t];
    const float bb  = b2[t];
    const float w64 = W1[64 * HID + t], w65 = W1[65 * HID + t], w66 = W1[66 * HID + t];
    const float NEG_INF = __int_as_float(0xff800000);

    __shared__ float vbuf[2][HID];

    for (int cc = 0; cc < CV_CENT; cc++) {
        const int ci = blockIdx.x * CV_CENT + cc;
        const float sx = g_selpos[3 * ci], sy = g_selpos[3 * ci + 1], sz = g_selpos[3 * ci + 2];
        float tsub = fmaf(sx, w64, fmaf(sy, w65, __fmul_rn(sz, w66)));
        const int cnt = g_ncnt[ci];
        const int* nb = &g_nbr[ci * KNBR];

        float acc = NEG_INF;
        float r0 = 0.f;
        if (cnt > 0) r0 = g_hpre[nb[0] * HID + t];
        for (int k = 0; k < cnt; k++) {
            const int buf = k & 1;
            vbuf[buf][t] = fmaxf(r0 - tsub, 0.f);
            if (k + 1 < cnt) r0 = g_hpre[nb[k + 1] * HID + t];
            __syncthreads();
            float y = 0.f;
            const float4* v4 = (const float4*)vbuf[buf];
#pragma unroll
            for (int h4 = 0; h4 < HID / 4; h4++) {
                float4 v = v4[h4];
                y = fmaf(v.x, w2c[4 * h4 + 0], y);
                y = fmaf(v.y, w2c[4 * h4 + 1], y);
                y = fmaf(v.z, w2c[4 * h4 + 2], y);
                y = fmaf(v.w, w2c[4 * h4 + 3], y);
            }
            acc = fmaxf(acc, y);
        }
        const int o = ci * OUTC + t;
        if (o < out_size) dout[o] = acc + bb;
        __syncthreads();   // protect vbuf across centroids
    }
}

// ===========================================================================
// Epilogue: sel_pos into d_out after the feature block; zero everything else
// (sel_batch is all-zero in every plausible dtype packing).
// ===========================================================================
__global__ void epilogue_kernel(float* __restrict__ dout, int out_size)
{
    const int i = blockIdx.x * blockDim.x + threadIdx.x;
    const long long idx = (long long)MSEL * OUTC + i;
    if (idx < (long long)out_size)
        dout[idx] = (i < MSEL * 3) ? g_selpos[i] : 0.0f;
}

// ===========================================================================
// Launch
// ===========================================================================
extern "C" void kernel_launch(void* const* d_in, const int* in_sizes, int n_in,
                              void* d_out, int out_size)
{
    if (n_in < 7) return;
    const float* x   = (const float*)d_in[0];
    const float* pos = (const float*)d_in[1];
    // d_in[2] = batch (all zeros, int64) — unused
    const float* W1  = (const float*)d_in[3];
    const float* b1  = (const float*)d_in[4];
    const float* W2  = (const float*)d_in[5];
    const float* b2  = (const float*)d_in[6];
    float* out = (float*)d_out;

    // Stage A: FPS (one 4-CTA cluster)
    fps_kernel<<<4, FPS_THREADS>>>(pos);

    // Stage C0: per-point layer-1 preactivations (independent of FPS)
    hpre_kernel<<<NPTS / 64, 128>>>(x, pos, W1, b1);

    // Stage B: radius neighbors
    cudaFuncSetAttribute(nbr_kernel, cudaFuncAttributeMaxDynamicSharedMemorySize, NB_SMEM);
    nbr_kernel<<<MSEL / NB_CPB, NB_THREADS, NB_SMEM>>>(pos);

    // Stage C: PointConv + masked max
    conv_kernel<<<MSEL / CV_CENT, 128>>>(W1, W2, b2, out, out_size);

    // Epilogue: sel_pos + zero fill of the batch/tail region
    const int tail = out_size - MSEL * OUTC;
    if (tail > 0)
        epilogue_kernel<<<(tail + 255) / 256, 256>>>(out, out_size);
}

// round 11
// speedup vs baseline: 1.3621x; 1.3621x over previous
#include <cuda_runtime.h>
#include <cuda_bf16.h>
#include <cstdint>

// ---------------------------------------------------------------------------
// Problem constants
// ---------------------------------------------------------------------------
#define NPTS   32768
#define FCH    64
#define MSEL   8192
#define KNBR   64
#define HID    128
#define OUTC   128

// ---------------------------------------------------------------------------
// Scratch (device globals; no allocation allowed)
// ---------------------------------------------------------------------------
__device__ float g_selpos[MSEL * 3];                 // FPS-selected positions
__device__ float g_hpre[NPTS * HID];                 // per-point layer-1 pre-activation
__device__ int   g_nbr[MSEL * KNBR];                 // neighbor indices (valid [0,cnt))
__device__ int   g_ncnt[MSEL];                       // neighbor counts

// spatial-sort scratch for FPS
#define NCELL 4096                                   // 16x16x16 Morton cells
__device__ int   g_ccnt[NCELL];
__device__ int   g_coff[NCELL];
__device__ float g_sx[NPTS], g_sy[NPTS], g_sz[NPTS];
__device__ int   g_sidx[NPTS];

__device__ __forceinline__ float d2_exact(float dx, float dy, float dz) {
    // Match XLA: elementwise square then add-reduce, NO fma contraction.
    return __fadd_rn(__fadd_rn(__fmul_rn(dx, dx), __fmul_rn(dy, dy)),
                     __fmul_rn(dz, dz));
}

__device__ __forceinline__ int cell_of(float x, float y, float z) {
    int cx = min(15, max(0, (int)(x * 16.0f)));
    int cy = min(15, max(0, (int)(y * 16.0f)));
    int cz = min(15, max(0, (int)(z * 16.0f)));
    int code = 0;
#pragma unroll
    for (int b = 0; b < 4; b++) {
        code |= ((cx >> b) & 1) << (3 * b);
        code |= ((cy >> b) & 1) << (3 * b + 1);
        code |= ((cz >> b) & 1) << (3 * b + 2);
    }
    return code;
}

// ===========================================================================
// Prep: Morton-cell counting sort of points (spatial buckets for FPS pruning)
// ===========================================================================
__global__ void zero_cells_kernel() {
    int i = blockIdx.x * blockDim.x + threadIdx.x;
    if (i < NCELL) g_ccnt[i] = 0;
}

__global__ void count_cells_kernel(const float* __restrict__ pos) {
    int i = blockIdx.x * blockDim.x + threadIdx.x;
    if (i < NPTS)
        atomicAdd(&g_ccnt[cell_of(pos[3 * i], pos[3 * i + 1], pos[3 * i + 2])], 1);
}

__global__ void __launch_bounds__(1024) scan_cells_kernel() {
    __shared__ int a[NCELL], b[NCELL];
    const int tid = threadIdx.x;
    for (int s = tid; s < NCELL; s += 1024) a[s] = g_ccnt[s];
    __syncthreads();
    int* src = a; int* dst = b;
    for (int off = 1; off < NCELL; off <<= 1) {
        for (int s = tid; s < NCELL; s += 1024)
            dst[s] = src[s] + ((s >= off) ? src[s - off] : 0);
        __syncthreads();
        int* t = src; src = dst; dst = t;
    }
    for (int s = tid; s < NCELL; s += 1024)
        g_coff[s] = (s ? src[s - 1] : 0);            // exclusive base (atomic cursor)
}

__global__ void scatter_kernel(const float* __restrict__ pos) {
    int i = blockIdx.x * blockDim.x + threadIdx.x;
    if (i >= NPTS) return;
    float x = pos[3 * i], y = pos[3 * i + 1], z = pos[3 * i + 2];
    int slot = atomicAdd(&g_coff[cell_of(x, y, z)], 1);
    g_sx[slot] = x; g_sy[slot] = y; g_sz[slot] = z; g_sidx[slot] = i;
}

// ===========================================================================
// Stage A: farthest point sampling with bucket pruning.
// 4-CTA cluster x 512 threads; each thread owns 16 spatially-contiguous
// (Morton-sorted) points + their bbox in registers. Per iteration, a bucket
// rescans only if the winner's conservative lower-bound distance to the bbox
// is below the bucket's cached max-min_d. Candidates reduce as packed u64
// keys (value desc, orig-index asc tie-break); winner xyz recovered via
// ballot-match + shfl.idx. Cross-CTA exchange: DSMEM mailbox + cluster barrier.
// ===========================================================================
#define FPS_THREADS 512
#define FPS_PTS     16

__global__ void __cluster_dims__(4, 1, 1) __launch_bounds__(FPS_THREADS, 1)
fps_kernel(const float* __restrict__ pos)
{
    __shared__ unsigned long long swkey[16];
    __shared__ float swx[16], swy[16], swz[16];
    __shared__ unsigned long long mbox[2][4][3];   // [parity][src rank][key, xy, z]

    const int tid  = threadIdx.x;
    const int rank = blockIdx.x;                    // grid = one 4-CTA cluster
    const int lane = tid & 31;
    const int warp = tid >> 5;
    const float POS_INF = __int_as_float(0x7f800000);

    float px[FPS_PTS], py[FPS_PTS], pz[FPS_PTS], mind[FPS_PTS];
    int   oid[FPS_PTS];
    const int base = (rank * FPS_THREADS + tid) * FPS_PTS;

    float bxmin = POS_INF, bxmax = -POS_INF;
    float bymin = POS_INF, bymax = -POS_INF;
    float bzmin = POS_INF, bzmax = -POS_INF;
#pragma unroll
    for (int j = 0; j < FPS_PTS; j++) {
        px[j] = g_sx[base + j]; py[j] = g_sy[base + j]; pz[j] = g_sz[base + j];
        oid[j] = g_sidx[base + j];
        mind[j] = POS_INF;
        bxmin = fminf(bxmin, px[j]); bxmax = fmaxf(bxmax, px[j]);
        bymin = fminf(bymin, py[j]); bymax = fmaxf(bymax, py[j]);
        bzmin = fminf(bzmin, pz[j]); bzmax = fmaxf(bzmax, pz[j]);
    }

    // winner = original point 0 (seed)
    float wx = pos[0], wy = pos[1], wz = pos[2];
    if (rank == 0 && tid == 0) {
        g_selpos[0] = wx; g_selpos[1] = wy; g_selpos[2] = wz;
    }

    // cached bucket candidate: value bv (=bucket max min_d), orig idx boi, pos
    float bv = POS_INF;                 // forces rescan on iteration 1
    int   boi = 0;
    float bx = 0.f, by = 0.f, bz = 0.f;

    for (int i = 1; i < MSEL; ++i) {
        // ---- conservative lower bound d2(winner, bbox), rounded DOWN ----
        float gx = fmaxf(fmaxf(__fsub_rd(bxmin, wx), __fsub_rd(wx, bxmax)), 0.f);
        float gy = fmaxf(fmaxf(__fsub_rd(bymin, wy), __fsub_rd(wy, bymax)), 0.f);
        float gz = fmaxf(fmaxf(__fsub_rd(bzmin, wz), __fsub_rd(wz, bzmax)), 0.f);
        float lb = __fmul_rd(
            __fadd_rd(__fadd_rd(__fmul_rd(gx, gx), __fmul_rd(gy, gy)),
                      __fmul_rd(gz, gz)),
            0.999998f);

        if (lb < bv) {   // bucket may change: exact rescan (rare after warmup)
            float nbv = -1.0f; int nboi = 0x7fffffff;
            float nx = 0.f, ny = 0.f, nz = 0.f;
#pragma unroll
            for (int j = 0; j < FPS_PTS; j++) {
                float dx = px[j] - wx, dy = py[j] - wy, dz = pz[j] - wz;
                float d2 = d2_exact(dx, dy, dz);
                float m  = fminf(mind[j], d2);
                mind[j]  = m;
                bool better = (m > nbv) || (m == nbv && oid[j] < nboi);
                if (better) { nbv = m; nboi = oid[j]; nx = px[j]; ny = py[j]; nz = pz[j]; }
            }
            bv = nbv; boi = nboi; bx = nx; by = ny; bz = nz;
        }

        // ---- packed key: value desc, then smallest orig index ----
        unsigned long long key =
            ((unsigned long long)__float_as_uint(bv) << 32) |
            (unsigned long long)(~(unsigned)boi);

        // warp butterfly max on key
        unsigned long long k = key;
#pragma unroll
        for (int off = 16; off; off >>= 1) {
            unsigned long long o = __shfl_xor_sync(0xffffffffu, k, off);
            if (o > k) k = o;
        }
        unsigned ball = __ballot_sync(0xffffffffu, key == k);
        int src = __ffs(ball) - 1;
        float kx = __shfl_sync(0xffffffffu, bx, src);
        float ky = __shfl_sync(0xffffffffu, by, src);
        float kz = __shfl_sync(0xffffffffu, bz, src);
        if (lane == 0) { swkey[warp] = k; swx[warp] = kx; swy[warp] = ky; swz[warp] = kz; }
        __syncthreads();

        const int par = i & 1;
        if (warp == 0) {
            unsigned long long myk = (lane < 16) ? swkey[lane] : 0ull;
            unsigned long long k2  = myk;
#pragma unroll
            for (int off = 8; off; off >>= 1) {
                unsigned long long o = __shfl_xor_sync(0xffffffffu, k2, off);
                if (o > k2) k2 = o;
            }
            unsigned b2 = __ballot_sync(0xffffffffu, myk == k2) & 0xffffu;
            int s2 = __ffs(b2) - 1;
            float X = __shfl_sync(0xffffffffu, (lane < 16) ? swx[lane] : 0.f, s2);
            float Y = __shfl_sync(0xffffffffu, (lane < 16) ? swy[lane] : 0.f, s2);
            float Z = __shfl_sync(0xffffffffu, (lane < 16) ? swz[lane] : 0.f, s2);

            if (lane < 4) {   // lane L -> deliver this CTA's candidate to rank L
                uint32_t la = (uint32_t)__cvta_generic_to_shared(&mbox[par][rank][0]);
                uint32_t ra;
                asm volatile("mapa.shared::cluster.u32 %0, %1, %2;"
                             : "=r"(ra) : "r"(la), "r"((unsigned)lane));
                unsigned long long xy =
                    ((unsigned long long)__float_as_uint(Y) << 32) | __float_as_uint(X);
                unsigned long long zz = (unsigned long long)__float_as_uint(Z);
                asm volatile("st.shared::cluster.b64 [%0],    %1;" :: "r"(ra), "l"(k2) : "memory");
                asm volatile("st.shared::cluster.b64 [%0+8],  %1;" :: "r"(ra), "l"(xy) : "memory");
                asm volatile("st.shared::cluster.b64 [%0+16], %1;" :: "r"(ra), "l"(zz) : "memory");
            }
        }
        // release (our stores) / acquire (remote stores)
        asm volatile("barrier.cluster.arrive.aligned;" ::: "memory");
        asm volatile("barrier.cluster.wait.aligned;"   ::: "memory");

        // ---- every thread computes the identical global winner ----
        unsigned long long wk = 0ull, wxy = 0ull, wzz = 0ull;
#pragma unroll
        for (int r = 0; r < 4; r++) {
            unsigned long long kk = mbox[par][r][0];
            if (kk > wk) { wk = kk; wxy = mbox[par][r][1]; wzz = mbox[par][r][2]; }
        }
        wx = __uint_as_float((unsigned)wxy);
        wy = __uint_as_float((unsigned)(wxy >> 32));
        wz = __uint_as_float((unsigned)wzz);

        if (rank == 0 && tid == 0) {
            g_selpos[3 * i]     = wx;
            g_selpos[3 * i + 1] = wy;
            g_selpos[3 * i + 2] = wz;
        }
    }
}

// ===========================================================================
// Stage C0: h_pre[j][ch] = b1[ch] + x[j,:]@W1[:64,ch] + pos[j,:]@W1[64:67,ch]
// ===========================================================================
__global__ void __launch_bounds__(128)
hpre_kernel(const float* __restrict__ x, const float* __restrict__ pos,
            const float* __restrict__ W1, const float* __restrict__ b1)
{
    const int t = threadIdx.x;
    float w1c[FCH + 3];
#pragma unroll
    for (int f = 0; f < FCH + 3; f++) w1c[f] = W1[f * HID + t];
    const float bb = b1[t];

    __shared__ float xs[FCH];
    __shared__ float ps[3];

    const int row0 = blockIdx.x * 64;
    for (int r = 0; r < 64; r++) {
        const int row = row0 + r;
        if (t < FCH) xs[t] = x[row * FCH + t];
        if (t < 3)   ps[t] = pos[row * 3 + t];
        __syncthreads();
        float acc = bb;
        acc = fmaf(ps[0], w1c[64], acc);
        acc = fmaf(ps[1], w1c[65], acc);
        acc = fmaf(ps[2], w1c[66], acc);
#pragma unroll
        for (int f = 0; f < FCH; f++) acc = fmaf(xs[f], w1c[f], acc);
        g_hpre[row * HID + t] = acc;
        __syncthreads();
    }
}

// ===========================================================================
// Stage B: radius neighbors (unchanged from passing round-9 kernel)
// ===========================================================================
#define NB_THREADS 256
#define NB_CPW     4
#define NB_CPB     32
#define NB_TILE    2048
#define NB_CAP     256
#define NB_SMEM    (NB_TILE * 16 + NB_CPB * NB_CAP * 8)

__global__ void __launch_bounds__(NB_THREADS)
nbr_kernel(const float* __restrict__ pos)
{
    extern __shared__ char smemraw[];
    float4* ptile = (float4*)smemraw;
    unsigned long long (*cand)[NB_CAP] =
        (unsigned long long (*)[NB_CAP])(smemraw + NB_TILE * 16);

    const int lane  = threadIdx.x & 31;
    const int warp  = threadIdx.x >> 5;
    const int cbase = blockIdx.x * NB_CPB + warp * NB_CPW;
    const float R2  = (float)(0.08 * 0.08);

    float cx[NB_CPW], cy[NB_CPW], cz[NB_CPW];
    int cnt[NB_CPW];
#pragma unroll
    for (int c = 0; c < NB_CPW; c++) {
        int ci = cbase + c;
        cx[c] = g_selpos[3 * ci]; cy[c] = g_selpos[3 * ci + 1]; cz[c] = g_selpos[3 * ci + 2];
        cnt[c] = 0;
    }

    for (int tb = 0; tb < NPTS; tb += NB_TILE) {
        __syncthreads();
        for (int s = threadIdx.x; s < NB_TILE; s += NB_THREADS) {
            int g = tb + s;
            ptile[s] = make_float4(pos[3 * g], pos[3 * g + 1], pos[3 * g + 2], 0.f);
        }
        __syncthreads();
#pragma unroll
        for (int c = 0; c < NB_CPW; c++) {
            const int row = warp * NB_CPW + c;
            for (int s = lane; s < NB_TILE; s += 32) {
                float4 p = ptile[s];
                float d2 = d2_exact(cx[c] - p.x, cy[c] - p.y, cz[c] - p.z);
                bool pred = (d2 <= R2);
                unsigned m = __ballot_sync(0xffffffffu, pred);
                if (pred) {
                    int slot = cnt[c] + __popc(m & ((1u << lane) - 1u));
                    if (slot < NB_CAP)
                        cand[row][slot] =
                            ((unsigned long long)__float_as_uint(d2) << 32) |
                            (unsigned)(tb + s);
                }
                cnt[c] += __popc(m);
            }
        }
    }

#pragma unroll
    for (int c = 0; c < NB_CPW; c++) {
        const int row = warp * NB_CPW + c;
        const int ci  = cbase + c;
        const int n   = min(cnt[c], NB_CAP);
        unsigned long long* a = cand[row];
        for (int e = lane; e < NB_CAP; e += 32)
            if (e >= n) a[e] = 0xffffffffffffffffull;
        __syncwarp();
        for (int k = 2; k <= NB_CAP; k <<= 1) {
            for (int j = k >> 1; j > 0; j >>= 1) {
                __syncwarp();
                for (int e = lane; e < NB_CAP; e += 32) {
                    int p = e ^ j;
                    if (p > e) {
                        unsigned long long va = a[e], vb = a[p];
                        bool up = ((e & k) == 0);
                        if ((va > vb) == up) { a[e] = vb; a[p] = va; }
                    }
                }
            }
        }
        __syncwarp();
        const int m = min(n, KNBR);
        for (int k = lane; k < KNBR; k += 32)
            g_nbr[ci * KNBR + k] = (k < m) ? (int)(a[k] & 0xffffffffu) : -1;
        if (lane == 0) g_ncnt[ci] = m;
        __syncwarp();
    }
}

// ===========================================================================
// Stage C: PointConv + masked max (unchanged from passing round-9 kernel)
// ===========================================================================
#define CV_CENT 16

__global__ void __launch_bounds__(128)
conv_kernel(const float* __restrict__ W1, const float* __restrict__ W2,
            const float* __restrict__ b2, float* __restrict__ dout, int out_size)
{
    const int t = threadIdx.x;
    float w2c[HID];
#pragma unroll
    for (int h = 0; h < HID; h++) w2c[h] = W2[h * OUTC + t];
    const float bb  = b2[t];
    const float w64 = W1[64 * HID + t], w65 = W1[65 * HID + t], w66 = W1[66 * HID + t];
    const float NEG_INF = __int_as_float(0xff800000);

    __shared__ float vbuf[2][HID];

    for (int cc = 0; cc < CV_CENT; cc++) {
        const int ci = blockIdx.x * CV_CENT + cc;
        const float sx = g_selpos[3 * ci], sy = g_selpos[3 * ci + 1], sz = g_selpos[3 * ci + 2];
        float tsub = fmaf(sx, w64, fmaf(sy, w65, __fmul_rn(sz, w66)));
        const int cnt = g_ncnt[ci];
        const int* nb = &g_nbr[ci * KNBR];

        float acc = NEG_INF;
        float r0 = 0.f;
        if (cnt > 0) r0 = g_hpre[nb[0] * HID + t];
        for (int k = 0; k < cnt; k++) {
            const int buf = k & 1;
            vbuf[buf][t] = fmaxf(r0 - tsub, 0.f);
            if (k + 1 < cnt) r0 = g_hpre[nb[k + 1] * HID + t];
            __syncthreads();
            float y = 0.f;
            const float4* v4 = (const float4*)vbuf[buf];
#pragma unroll
            for (int h4 = 0; h4 < HID / 4; h4++) {
                float4 v = v4[h4];
                y = fmaf(v.x, w2c[4 * h4 + 0], y);
                y = fmaf(v.y, w2c[4 * h4 + 1], y);
                y = fmaf(v.z, w2c[4 * h4 + 2], y);
                y = fmaf(v.w, w2c[4 * h4 + 3], y);
            }
            acc = fmaxf(acc, y);
        }
        const int o = ci * OUTC + t;
        if (o < out_size) dout[o] = acc + bb;
        __syncthreads();
    }
}

// ===========================================================================
// Epilogue: sel_pos after the feature block; zero the rest (sel_batch = 0)
// ===========================================================================
__global__ void epilogue_kernel(float* __restrict__ dout, int out_size)
{
    const int i = blockIdx.x * blockDim.x + threadIdx.x;
    const long long idx = (long long)MSEL * OUTC + i;
    if (idx < (long long)out_size)
        dout[idx] = (i < MSEL * 3) ? g_selpos[i] : 0.0f;
}

// ===========================================================================
// Launch
// ===========================================================================
extern "C" void kernel_launch(void* const* d_in, const int* in_sizes, int n_in,
                              void* d_out, int out_size)
{
    if (n_in < 7) return;
    const float* x   = (const float*)d_in[0];
    const float* pos = (const float*)d_in[1];
    // d_in[2] = batch (all zeros, int64) — unused
    const float* W1  = (const float*)d_in[3];
    const float* b1  = (const float*)d_in[4];
    const float* W2  = (const float*)d_in[5];
    const float* b2  = (const float*)d_in[6];
    float* out = (float*)d_out;

    // Prep: Morton counting-sort of points into 2048 spatial buckets
    zero_cells_kernel<<<(NCELL + 255) / 256, 256>>>();
    count_cells_kernel<<<(NPTS + 255) / 256, 256>>>(pos);
    scan_cells_kernel<<<1, 1024>>>();
    scatter_kernel<<<(NPTS + 255) / 256, 256>>>(pos);

    // Stage A: FPS with bucket pruning (one 4-CTA cluster)
    fps_kernel<<<4, FPS_THREADS>>>(pos);

    // Stage C0: per-point layer-1 preactivations
    hpre_kernel<<<NPTS / 64, 128>>>(x, pos, W1, b1);

    // Stage B: radius neighbors
    cudaFuncSetAttribute(nbr_kernel, cudaFuncAttributeMaxDynamicSharedMemorySize, NB_SMEM);
    nbr_kernel<<<MSEL / NB_CPB, NB_THREADS, NB_SMEM>>>(pos);

    // Stage C: PointConv + masked max
    conv_kernel<<<MSEL / CV_CENT, 128>>>(W1, W2, b2, out, out_size);

    // Epilogue: sel_pos + zero fill
    const int tail = out_size - MSEL * OUTC;
    if (tail > 0)
        epilogue_kernel<<<(tail + 255) / 256, 256>>>(out, out_size);
}

// round 12
// speedup vs baseline: 1.3903x; 1.0207x over previous
#include <cuda_runtime.h>
#include <cuda_bf16.h>
#include <cstdint>

// ---------------------------------------------------------------------------
// Problem constants
// ---------------------------------------------------------------------------
#define NPTS   32768
#define FCH    64
#define MSEL   8192
#define KNBR   64
#define HID    128
#define OUTC   128

// ---------------------------------------------------------------------------
// Scratch (device globals; no allocation allowed)
// ---------------------------------------------------------------------------
__device__ float g_selpos[MSEL * 3];
__device__ float g_hpre[NPTS * HID];
__device__ int   g_nbr[MSEL * KNBR];
__device__ int   g_ncnt[MSEL];

// spatial-sort scratch for FPS
#define NCELL 4096                                   // 16x16x16 Morton cells
__device__ int   g_ccnt[NCELL];
__device__ int   g_coff[NCELL];
__device__ float g_sx[NPTS], g_sy[NPTS], g_sz[NPTS];
__device__ int   g_sidx[NPTS];

__device__ __forceinline__ float d2_exact(float dx, float dy, float dz) {
    // Match XLA: elementwise square then add-reduce, NO fma contraction.
    return __fadd_rn(__fadd_rn(__fmul_rn(dx, dx), __fmul_rn(dy, dy)),
                     __fmul_rn(dz, dz));
}

__device__ __forceinline__ int cell_of(float x, float y, float z) {
    int cx = min(15, max(0, (int)(x * 16.0f)));
    int cy = min(15, max(0, (int)(y * 16.0f)));
    int cz = min(15, max(0, (int)(z * 16.0f)));
    int code = 0;
#pragma unroll
    for (int b = 0; b < 4; b++) {
        code |= ((cx >> b) & 1) << (3 * b);
        code |= ((cy >> b) & 1) << (3 * b + 1);
        code |= ((cz >> b) & 1) << (3 * b + 2);
    }
    return code;
}

// ===========================================================================
// Prep: Morton-cell counting sort of points
// ===========================================================================
__global__ void zero_cells_kernel() {
    int i = blockIdx.x * blockDim.x + threadIdx.x;
    if (i < NCELL) g_ccnt[i] = 0;
}

__global__ void count_cells_kernel(const float* __restrict__ pos) {
    int i = blockIdx.x * blockDim.x + threadIdx.x;
    if (i < NPTS)
        atomicAdd(&g_ccnt[cell_of(pos[3 * i], pos[3 * i + 1], pos[3 * i + 2])], 1);
}

__global__ void __launch_bounds__(1024) scan_cells_kernel() {
    __shared__ int a[NCELL], b[NCELL];
    const int tid = threadIdx.x;
    for (int s = tid; s < NCELL; s += 1024) a[s] = g_ccnt[s];
    __syncthreads();
    int* src = a; int* dst = b;
    for (int off = 1; off < NCELL; off <<= 1) {
        for (int s = tid; s < NCELL; s += 1024)
            dst[s] = src[s] + ((s >= off) ? src[s - off] : 0);
        __syncthreads();
        int* t = src; src = dst; dst = t;
    }
    for (int s = tid; s < NCELL; s += 1024)
        g_coff[s] = (s ? src[s - 1] : 0);
}

__global__ void scatter_kernel(const float* __restrict__ pos) {
    int i = blockIdx.x * blockDim.x + threadIdx.x;
    if (i >= NPTS) return;
    float x = pos[3 * i], y = pos[3 * i + 1], z = pos[3 * i + 2];
    int slot = atomicAdd(&g_coff[cell_of(x, y, z)], 1);
    g_sx[slot] = x; g_sy[slot] = y; g_sz[slot] = z; g_sidx[slot] = i;
}

// ===========================================================================
// Stage A: FPS with bucket pruning.
// Exchange: mbarrier mailbox (no barrier.cluster in the loop).
// Reductions: REDUX.SYNC (max on value bits, min on masked orig index).
// ===========================================================================
#define FPS_THREADS 512
#define FPS_PTS     16

__global__ void __cluster_dims__(4, 1, 1) __launch_bounds__(FPS_THREADS, 1)
fps_kernel(const float* __restrict__ pos)
{
    __shared__ unsigned swv[16];      // per-warp best value bits
    __shared__ unsigned swo[16];      // per-warp best orig idx
    __shared__ float    swx[16], swy[16], swz[16];
    __shared__ unsigned long long mbox[2][4][3];   // [parity][src rank][key, xy, z]
    __shared__ __align__(8) unsigned long long mbar[2];

    const int tid  = threadIdx.x;
    const int rank = blockIdx.x;                    // grid = one 4-CTA cluster
    const int lane = tid & 31;
    const int warp = tid >> 5;
    const float POS_INF = __int_as_float(0x7f800000);

    // init mbarriers (count = 4 arrivals: one per CTA)
    if (tid == 0) {
        uint32_t a0 = (uint32_t)__cvta_generic_to_shared(&mbar[0]);
        uint32_t a1 = (uint32_t)__cvta_generic_to_shared(&mbar[1]);
        asm volatile("mbarrier.init.shared.b64 [%0], %1;" :: "r"(a0), "r"(4u) : "memory");
        asm volatile("mbarrier.init.shared.b64 [%0], %1;" :: "r"(a1), "r"(4u) : "memory");
    }
    __syncthreads();
    asm volatile("barrier.cluster.arrive.aligned;" ::: "memory");
    asm volatile("barrier.cluster.wait.aligned;"   ::: "memory");

    float px[FPS_PTS], py[FPS_PTS], pz[FPS_PTS], mind[FPS_PTS];
    int   oid[FPS_PTS];
    const int base = (rank * FPS_THREADS + tid) * FPS_PTS;

    float bxmin = POS_INF, bxmax = -POS_INF;
    float bymin = POS_INF, bymax = -POS_INF;
    float bzmin = POS_INF, bzmax = -POS_INF;
#pragma unroll
    for (int j = 0; j < FPS_PTS; j++) {
        px[j] = g_sx[base + j]; py[j] = g_sy[base + j]; pz[j] = g_sz[base + j];
        oid[j] = g_sidx[base + j];
        mind[j] = POS_INF;
        bxmin = fminf(bxmin, px[j]); bxmax = fmaxf(bxmax, px[j]);
        bymin = fminf(bymin, py[j]); bymax = fmaxf(bymax, py[j]);
        bzmin = fminf(bzmin, pz[j]); bzmax = fmaxf(bzmax, pz[j]);
    }

    float wx = pos[0], wy = pos[1], wz = pos[2];
    if (rank == 0 && tid == 0) {
        g_selpos[0] = wx; g_selpos[1] = wy; g_selpos[2] = wz;
    }

    // cached bucket candidate
    float bv = POS_INF;                 // forces rescan on iteration 1
    unsigned boi = 0u;
    float bx = 0.f, by = 0.f, bz = 0.f;

    for (int i = 1; i < MSEL; ++i) {
        // conservative (round-down) lower bound d2(winner, bucket bbox)
        float gx = fmaxf(fmaxf(__fsub_rd(bxmin, wx), __fsub_rd(wx, bxmax)), 0.f);
        float gy = fmaxf(fmaxf(__fsub_rd(bymin, wy), __fsub_rd(wy, bymax)), 0.f);
        float gz = fmaxf(fmaxf(__fsub_rd(bzmin, wz), __fsub_rd(wz, bzmax)), 0.f);
        float lb = __fmul_rd(
            __fadd_rd(__fadd_rd(__fmul_rd(gx, gx), __fmul_rd(gy, gy)),
                      __fmul_rd(gz, gz)),
            0.999998f);

        if (lb < bv) {   // exact rescan (rare after warmup)
            float nbv = -1.0f; unsigned nboi = 0xffffffffu;
            float nx = 0.f, ny = 0.f, nz = 0.f;
#pragma unroll
            for (int j = 0; j < FPS_PTS; j++) {
                float dx = px[j] - wx, dy = py[j] - wy, dz = pz[j] - wz;
                float d2 = d2_exact(dx, dy, dz);
                float m  = fminf(mind[j], d2);
                mind[j]  = m;
                bool better = (m > nbv) || (m == nbv && (unsigned)oid[j] < nboi);
                if (better) { nbv = m; nboi = (unsigned)oid[j]; nx = px[j]; ny = py[j]; nz = pz[j]; }
            }
            bv = nbv; boi = nboi; bx = nx; by = ny; bz = nz;
        }

        // ---- warp reduce via REDUX: max value bits, then min orig idx among ties
        unsigned vb   = __float_as_uint(bv);              // bv >= 0 -> order-preserving
        unsigned vmax = __reduce_max_sync(0xffffffffu, vb);
        unsigned oc   = (vb == vmax) ? boi : 0xffffffffu;
        unsigned omin = __reduce_min_sync(0xffffffffu, oc);
        unsigned ball = __ballot_sync(0xffffffffu, oc == omin);
        int src = __ffs(ball) - 1;
        float kx = __shfl_sync(0xffffffffu, bx, src);
        float ky = __shfl_sync(0xffffffffu, by, src);
        float kz = __shfl_sync(0xffffffffu, bz, src);
        if (lane == 0) { swv[warp] = vmax; swo[warp] = omin; swx[warp] = kx; swy[warp] = ky; swz[warp] = kz; }
        __syncthreads();

        const int par = i & 1;
        if (warp == 0) {
            unsigned v2 = (lane < 16) ? swv[lane] : 0u;
            unsigned o2 = (lane < 16) ? swo[lane] : 0xffffffffu;
            float    X2 = (lane < 16) ? swx[lane] : 0.f;
            float    Y2 = (lane < 16) ? swy[lane] : 0.f;
            float    Z2 = (lane < 16) ? swz[lane] : 0.f;
            unsigned vmax2 = __reduce_max_sync(0xffffffffu, v2);
            unsigned oc2   = (v2 == vmax2) ? o2 : 0xffffffffu;
            unsigned omin2 = __reduce_min_sync(0xffffffffu, oc2);
            unsigned b2    = __ballot_sync(0xffffffffu, oc2 == omin2);
            int s2 = __ffs(b2) - 1;
            float X = __shfl_sync(0xffffffffu, X2, s2);
            float Y = __shfl_sync(0xffffffffu, Y2, s2);
            float Z = __shfl_sync(0xffffffffu, Z2, s2);

            if (lane < 4) {   // deliver this CTA's candidate to cluster CTA 'lane'
                unsigned long long key =
                    ((unsigned long long)vmax2 << 32) | (unsigned long long)(~omin2);
                unsigned long long xy =
                    ((unsigned long long)__float_as_uint(Y) << 32) | __float_as_uint(X);
                unsigned long long zz = (unsigned long long)__float_as_uint(Z);
                uint32_t la = (uint32_t)__cvta_generic_to_shared(&mbox[par][rank][0]);
                uint32_t ra;
                asm volatile("mapa.shared::cluster.u32 %0, %1, %2;"
                             : "=r"(ra) : "r"(la), "r"((unsigned)lane));
                asm volatile("st.shared::cluster.b64 [%0],    %1;" :: "r"(ra), "l"(key) : "memory");
                asm volatile("st.shared::cluster.b64 [%0+8],  %1;" :: "r"(ra), "l"(xy)  : "memory");
                asm volatile("st.shared::cluster.b64 [%0+16], %1;" :: "r"(ra), "l"(zz)  : "memory");
                uint32_t lbv = (uint32_t)__cvta_generic_to_shared(&mbar[par]);
                uint32_t rb;
                asm volatile("mapa.shared::cluster.u32 %0, %1, %2;"
                             : "=r"(rb) : "r"(lbv), "r"((unsigned)lane));
                asm volatile("mbarrier.arrive.release.cluster.shared::cluster.b64 _, [%0];"
                             :: "r"(rb) : "memory");
            }
        }

        // ---- all threads wait for 4 arrivals on the local mbarrier
        {
            uint32_t bar = (uint32_t)__cvta_generic_to_shared(&mbar[par]);
            unsigned ph  = (unsigned)(((i - 1) >> 1) & 1);
            unsigned done;
            asm volatile(
                "{\n\t.reg .pred p;\n\t"
                "mbarrier.try_wait.parity.acquire.cluster.shared::cta.b64 p, [%1], %2, 0x989680;\n\t"
                "selp.b32 %0, 1, 0, p;\n\t}"
                : "=r"(done) : "r"(bar), "r"(ph) : "memory");
            while (!done) {
                asm volatile(
                    "{\n\t.reg .pred p;\n\t"
                    "mbarrier.try_wait.parity.acquire.cluster.shared::cta.b64 p, [%1], %2, 0x989680;\n\t"
                    "selp.b32 %0, 1, 0, p;\n\t}"
                    : "=r"(done) : "r"(bar), "r"(ph) : "memory");
            }
        }

        // ---- every thread computes the identical global winner
        unsigned long long wk = 0ull, wxy = 0ull, wzz = 0ull;
#pragma unroll
        for (int r = 0; r < 4; r++) {
            unsigned long long kk = mbox[par][r][0];
            if (kk > wk) { wk = kk; wxy = mbox[par][r][1]; wzz = mbox[par][r][2]; }
        }
        wx = __uint_as_float((unsigned)wxy);
        wy = __uint_as_float((unsigned)(wxy >> 32));
        wz = __uint_as_float((unsigned)wzz);

        if (rank == 0 && tid == 0) {
            g_selpos[3 * i]     = wx;
            g_selpos[3 * i + 1] = wy;
            g_selpos[3 * i + 2] = wz;
        }
    }

    asm volatile("barrier.cluster.arrive.aligned;" ::: "memory");
    asm volatile("barrier.cluster.wait.aligned;"   ::: "memory");
}

// ===========================================================================
// Stage C0: h_pre[j][ch] = b1[ch] + x[j,:]@W1[:64,ch] + pos[j,:]@W1[64:67,ch]
// ===========================================================================
__global__ void __launch_bounds__(128)
hpre_kernel(const float* __restrict__ x, const float* __restrict__ pos,
            const float* __restrict__ W1, const float* __restrict__ b1)
{
    const int t = threadIdx.x;
    float w1c[FCH + 3];
#pragma unroll
    for (int f = 0; f < FCH + 3; f++) w1c[f] = W1[f * HID + t];
    const float bb = b1[t];

    __shared__ float xs[FCH];
    __shared__ float ps[3];

    const int row0 = blockIdx.x * 64;
    for (int r = 0; r < 64; r++) {
        const int row = row0 + r;
        if (t < FCH) xs[t] = x[row * FCH + t];
        if (t < 3)   ps[t] = pos[row * 3 + t];
        __syncthreads();
        float acc = bb;
        acc = fmaf(ps[0], w1c[64], acc);
        acc = fmaf(ps[1], w1c[65], acc);
        acc = fmaf(ps[2], w1c[66], acc);
#pragma unroll
        for (int f = 0; f < FCH; f++) acc = fmaf(xs[f], w1c[f], acc);
        g_hpre[row * HID + t] = acc;
        __syncthreads();
    }
}

// ===========================================================================
// Stage B: radius neighbors (unchanged — correct & fast enough for now)
// ===========================================================================
#define NB_THREADS 256
#define NB_CPW     4
#define NB_CPB     32
#define NB_TILE    2048
#define NB_CAP     256
#define NB_SMEM    (NB_TILE * 16 + NB_CPB * NB_CAP * 8)

__global__ void __launch_bounds__(NB_THREADS)
nbr_kernel(const float* __restrict__ pos)
{
    extern __shared__ char smemraw[];
    float4* ptile = (float4*)smemraw;
    unsigned long long (*cand)[NB_CAP] =
        (unsigned long long (*)[NB_CAP])(smemraw + NB_TILE * 16);

    const int lane  = threadIdx.x & 31;
    const int warp  = threadIdx.x >> 5;
    const int cbase = blockIdx.x * NB_CPB + warp * NB_CPW;
    const float R2  = (float)(0.08 * 0.08);

    float cx[NB_CPW], cy[NB_CPW], cz[NB_CPW];
    int cnt[NB_CPW];
#pragma unroll
    for (int c = 0; c < NB_CPW; c++) {
        int ci = cbase + c;
        cx[c] = g_selpos[3 * ci]; cy[c] = g_selpos[3 * ci + 1]; cz[c] = g_selpos[3 * ci + 2];
        cnt[c] = 0;
    }

    for (int tb = 0; tb < NPTS; tb += NB_TILE) {
        __syncthreads();
        for (int s = threadIdx.x; s < NB_TILE; s += NB_THREADS) {
            int g = tb + s;
            ptile[s] = make_float4(pos[3 * g], pos[3 * g + 1], pos[3 * g + 2], 0.f);
        }
        __syncthreads();
#pragma unroll
        for (int c = 0; c < NB_CPW; c++) {
            const int row = warp * NB_CPW + c;
            for (int s = lane; s < NB_TILE; s += 32) {
                float4 p = ptile[s];
                float d2 = d2_exact(cx[c] - p.x, cy[c] - p.y, cz[c] - p.z);
                bool pred = (d2 <= R2);
                unsigned m = __ballot_sync(0xffffffffu, pred);
                if (pred) {
                    int slot = cnt[c] + __popc(m & ((1u << lane) - 1u));
                    if (slot < NB_CAP)
                        cand[row][slot] =
                            ((unsigned long long)__float_as_uint(d2) << 32) |
                            (unsigned)(tb + s);
                }
                cnt[c] += __popc(m);
            }
        }
    }

#pragma unroll
    for (int c = 0; c < NB_CPW; c++) {
        const int row = warp * NB_CPW + c;
        const int ci  = cbase + c;
        const int n   = min(cnt[c], NB_CAP);
        unsigned long long* a = cand[row];
        for (int e = lane; e < NB_CAP; e += 32)
            if (e >= n) a[e] = 0xffffffffffffffffull;
        __syncwarp();
        for (int k = 2; k <= NB_CAP; k <<= 1) {
            for (int j = k >> 1; j > 0; j >>= 1) {
                __syncwarp();
                for (int e = lane; e < NB_CAP; e += 32) {
                    int p = e ^ j;
                    if (p > e) {
                        unsigned long long va = a[e], vb = a[p];
                        bool up = ((e & k) == 0);
                        if ((va > vb) == up) { a[e] = vb; a[p] = va; }
                    }
                }
            }
        }
        __syncwarp();
        const int m = min(n, KNBR);
        for (int k = lane; k < KNBR; k += 32)
            g_nbr[ci * KNBR + k] = (k < m) ? (int)(a[k] & 0xffffffffu) : -1;
        if (lane == 0) g_ncnt[ci] = m;
        __syncwarp();
    }
}

// ===========================================================================
// Stage C: PointConv + masked max.
// 256 threads = two independent 128-thread halves (named barriers 1/2),
// 8-neighbor tiles, register prefetch, packed fp32x2 FMA (fma.rn.f32x2).
// ===========================================================================
#define CV_T     8
#define CV_PAIRS 8     // centroids per half per CTA

#define FMA2(d, a, b, c) \
    asm("fma.rn.f32x2 %0, %1, %2, %3;" : "=l"(d) : "l"(a), "l"(b), "l"(c))

__global__ void __launch_bounds__(256)
conv_kernel(const float* __restrict__ W1, const float* __restrict__ W2,
            const float* __restrict__ b2, float* __restrict__ dout, int out_size)
{
    const int half = threadIdx.x >> 7;          // 0 or 1
    const int t    = threadIdx.x & 127;
    const int barid = 1 + half;

    __shared__ __align__(16) float vbuf[2][CV_T][HID];

    // W2 columns packed as f32x2 pairs (registers)
    unsigned long long w2p[HID / 2];
#pragma unroll
    for (int h2 = 0; h2 < HID / 2; h2++) {
        float a = W2[(2 * h2) * OUTC + t];
        float b = W2[(2 * h2 + 1) * OUTC + t];
        asm("mov.b64 %0, {%1, %2};" : "=l"(w2p[h2]) : "f"(a), "f"(b));
    }
    const float bb  = b2[t];
    const float w64 = W1[64 * HID + t], w65 = W1[65 * HID + t], w66 = W1[66 * HID + t];
    const float NEG_INF = __int_as_float(0xff800000);

    for (int cc = 0; cc < CV_PAIRS; cc++) {
        const int ci = blockIdx.x * (2 * CV_PAIRS) + half * CV_PAIRS + cc;
        const float sx = g_selpos[3 * ci], sy = g_selpos[3 * ci + 1], sz = g_selpos[3 * ci + 2];
        const float tsub = fmaf(sx, w64, fmaf(sy, w65, __fmul_rn(sz, w66)));
        const int cnt = g_ncnt[ci];
        const int* nb = &g_nbr[ci * KNBR];

        float acc = NEG_INF;
        const int nt = (cnt + CV_T - 1) / CV_T;

        // prefetch first tile rows
        float r[CV_T];
#pragma unroll
        for (int j = 0; j < CV_T; j++)
            r[j] = (j < cnt) ? __ldg(&g_hpre[nb[j] * HID + t]) : 0.f;

        for (int tb = 0; tb < nt; tb++) {
            const int k0 = tb * CV_T;
            const int kn = min(CV_T, cnt - k0);

            // fill valid rows
#pragma unroll
            for (int j = 0; j < CV_T; j++)
                if (j < kn) vbuf[half][j][t] = fmaxf(r[j] - tsub, 0.f);
            asm volatile("bar.sync %0, 128;" :: "r"(barid) : "memory");

            // prefetch next tile (overlaps compute)
#pragma unroll
            for (int j = 0; j < CV_T; j++) {
                int kk = k0 + CV_T + j;
                if (kk < cnt) r[j] = __ldg(&g_hpre[nb[kk] * HID + t]);
            }

            // 8 dot products via packed fp32x2 FMA
            unsigned long long y2[CV_T];
#pragma unroll
            for (int j = 0; j < CV_T; j++) y2[j] = 0ull;
#pragma unroll
            for (int h4 = 0; h4 < HID / 4; h4++) {
#pragma unroll
                for (int j = 0; j < CV_T; j++) {
                    ulonglong2 p = *reinterpret_cast<const ulonglong2*>(
                        &vbuf[half][j][h4 * 4]);
                    FMA2(y2[j], p.x, w2p[2 * h4],     y2[j]);
                    FMA2(y2[j], p.y, w2p[2 * h4 + 1], y2[j]);
                }
            }
#pragma unroll
            for (int j = 0; j < CV_T; j++) {
                float lo = __uint_as_float((unsigned)y2[j]);
                float hi = __uint_as_float((unsigned)(y2[j] >> 32));
                float y  = lo + hi;
                if (j < kn) acc = fmaxf(acc, y);
            }
            asm volatile("bar.sync %0, 128;" :: "r"(barid) : "memory");
        }

        const int o = ci * OUTC + t;
        if (o < out_size) dout[o] = acc + bb;
    }
}

// ===========================================================================
// Epilogue: sel_pos after the feature block; zero the rest (sel_batch = 0)
// ===========================================================================
__global__ void epilogue_kernel(float* __restrict__ dout, int out_size)
{
    const int i = blockIdx.x * blockDim.x + threadIdx.x;
    const long long idx = (long long)MSEL * OUTC + i;
    if (idx < (long long)out_size)
        dout[idx] = (i < MSEL * 3) ? g_selpos[i] : 0.0f;
}

// ===========================================================================
// Launch
// ===========================================================================
extern "C" void kernel_launch(void* const* d_in, const int* in_sizes, int n_in,
                              void* d_out, int out_size)
{
    if (n_in < 7) return;
    const float* x   = (const float*)d_in[0];
    const float* pos = (const float*)d_in[1];
    // d_in[2] = batch (all zeros, int64) — unused
    const float* W1  = (const float*)d_in[3];
    const float* b1  = (const float*)d_in[4];
    const float* W2  = (const float*)d_in[5];
    const float* b2  = (const float*)d_in[6];
    float* out = (float*)d_out;

    // Prep: Morton counting-sort into 2048 spatial buckets
    zero_cells_kernel<<<(NCELL + 255) / 256, 256>>>();
    count_cells_kernel<<<(NPTS + 255) / 256, 256>>>(pos);
    scan_cells_kernel<<<1, 1024>>>();
    scatter_kernel<<<(NPTS + 255) / 256, 256>>>(pos);

    // Stage A: FPS (one 4-CTA cluster, mbarrier exchange)
    fps_kernel<<<4, FPS_THREADS>>>(pos);

    // Stage C0: per-point layer-1 preactivations
    hpre_kernel<<<NPTS / 64, 128>>>(x, pos, W1, b1);

    // Stage B: radius neighbors
    cudaFuncSetAttribute(nbr_kernel, cudaFuncAttributeMaxDynamicSharedMemorySize, NB_SMEM);
    nbr_kernel<<<MSEL / NB_CPB, NB_THREADS, NB_SMEM>>>(pos);

    // Stage C: PointConv + masked max (fp32x2, tiled)
    conv_kernel<<<MSEL / (2 * CV_PAIRS), 256>>>(W1, W2, b2, out, out_size);

    // Epilogue: sel_pos + zero fill
    const int tail = out_size - MSEL * OUTC;
    if (tail > 0)
        epilogue_kernel<<<(tail + 255) / 256, 256>>>(out, out_size);
}